// round 1
// baseline (speedup 1.0000x reference)
#include <cuda_runtime.h>
#include <math.h>

#define TPB 256

// ---------------------------------------------------------------------------
// Fused LoFTR locally-grouped linear-attention encoder layer.
// One block = one 8x8 window (64 tokens x 256 channels), all intermediates in
// shared memory. 3600 blocks, 256 threads.
//
// smem layout (floats):
//   xs   [64][256]   input window                 16384
//   bA   [64][256]   V -> Q -> m2(LN1)            16384
//   bB   [64][256]   K -> msg -> h1/h2 -> out2    16384
//   KV   [8*32][32]  per-head K^T V                8192
//   Ksum [256]                                      256
// total 57600 floats = 230400 bytes (<= 227KB optin limit)
// ---------------------------------------------------------------------------

__device__ __forceinline__ void gemm_k256(const float* __restrict__ A,
                                          const float* __restrict__ Wp,
                                          int ldw, int i, int j,
                                          float acc[16][4])
{
    // A: smem [64][256] row-major. Thread covers rows 16i..16i+15, cols 4j..4j+3.
    const float* arow0 = A + (i << 4) * 256;
#pragma unroll 4
    for (int k = 0; k < 256; ++k) {
        float4 wv = *reinterpret_cast<const float4*>(Wp + (size_t)k * ldw + (j << 2));
        const float* ap = arow0 + k;
#pragma unroll
        for (int r = 0; r < 16; ++r) {
            float a = ap[r * 256];
            acc[r][0] = fmaf(a, wv.x, acc[r][0]);
            acc[r][1] = fmaf(a, wv.y, acc[r][1]);
            acc[r][2] = fmaf(a, wv.z, acc[r][2]);
            acc[r][3] = fmaf(a, wv.w, acc[r][3]);
        }
    }
}

__device__ __forceinline__ void zero_acc(float acc[16][4])
{
#pragma unroll
    for (int r = 0; r < 16; ++r) {
        acc[r][0] = 0.f; acc[r][1] = 0.f; acc[r][2] = 0.f; acc[r][3] = 0.f;
    }
}

// MODE: 0 = plain, 1 = elu(x)+1, 2 = scale by 1/64, 3 = relu
template<int MODE>
__device__ __forceinline__ void store_acc(float* __restrict__ dst,
                                          float acc[16][4], int i, int j)
{
#pragma unroll
    for (int r = 0; r < 16; ++r) {
        float t0 = acc[r][0], t1 = acc[r][1], t2 = acc[r][2], t3 = acc[r][3];
        if (MODE == 1) {
            t0 = (t0 > 0.f) ? (t0 + 1.f) : __expf(t0);
            t1 = (t1 > 0.f) ? (t1 + 1.f) : __expf(t1);
            t2 = (t2 > 0.f) ? (t2 + 1.f) : __expf(t2);
            t3 = (t3 > 0.f) ? (t3 + 1.f) : __expf(t3);
        } else if (MODE == 2) {
            const float s = 1.0f / 64.0f;
            t0 *= s; t1 *= s; t2 *= s; t3 *= s;
        } else if (MODE == 3) {
            t0 = fmaxf(t0, 0.f); t1 = fmaxf(t1, 0.f);
            t2 = fmaxf(t2, 0.f); t3 = fmaxf(t3, 0.f);
        }
        float4 v; v.x = t0; v.y = t1; v.z = t2; v.w = t3;
        *reinterpret_cast<float4*>(dst + (((i << 4) + r) << 8) + (j << 2)) = v;
    }
}

extern __shared__ float smem[];

__global__ void __launch_bounds__(TPB, 1)
loftr_window_kernel(const float* __restrict__ x,
                    const float* __restrict__ Wq,
                    const float* __restrict__ Wk,
                    const float* __restrict__ Wv,
                    const float* __restrict__ Wm,
                    const float* __restrict__ W1,
                    const float* __restrict__ W2,
                    const float* __restrict__ g1,
                    const float* __restrict__ b1,
                    const float* __restrict__ g2,
                    const float* __restrict__ b2,
                    float* __restrict__ out)
{
    float* xs   = smem;
    float* bA   = xs + 64 * 256;
    float* bB   = bA + 64 * 256;
    float* KVs  = bB + 64 * 256;    // [256][32]  (h*32+d, dv)
    float* Ksum = KVs + 8192;       // [256]

    const int tid = threadIdx.x;
    const int wdx = blockIdx.x;
    const int bb  = wdx / 900;
    const int rem = wdx % 900;
    const int hi  = rem / 30;
    const int wi  = rem % 30;

    const float* xg = x + (size_t)bb * 57600 * 256;

    // ---- load window x into smem (coalesced float4) ----
    for (int idx = tid; idx < 64 * 64; idx += TPB) {
        int l  = idx >> 6;
        int c4 = idx & 63;
        int grow = (hi * 8 + (l >> 3)) * 240 + wi * 8 + (l & 7);
        *reinterpret_cast<float4*>(xs + l * 256 + c4 * 4) =
            *reinterpret_cast<const float4*>(xg + (size_t)grow * 256 + c4 * 4);
    }
    __syncthreads();

    const int i = tid >> 6;   // 0..3  (row group of 16)
    const int j = tid & 63;   // 0..63 (col group of 4)

    float acc[16][4];

    // ---- K = elu(x@Wk)+1 -> bB ----
    zero_acc(acc);
    gemm_k256(xs, Wk, 256, i, j, acc);
    store_acc<1>(bB, acc, i, j);

    // ---- V = (x@Wv)/64 -> bA ----
    zero_acc(acc);
    gemm_k256(xs, Wv, 256, i, j, acc);
    store_acc<2>(bA, acc, i, j);
    __syncthreads();

    // ---- Ksum[c] = sum_l K[l][c] ----
    {
        float s = 0.f;
#pragma unroll 8
        for (int l = 0; l < 64; ++l) s += bB[l * 256 + tid];
        Ksum[tid] = s;
    }

    // ---- KV[h][d][dv] = sum_l K[l][h,d] * V[l][h,dv] ----
    {
        const int h = tid >> 5, d = tid & 31;
        float kvv[32];
#pragma unroll
        for (int dv = 0; dv < 32; ++dv) kvv[dv] = 0.f;
        for (int l = 0; l < 64; ++l) {
            float kk = bB[l * 256 + h * 32 + d];
            const float* vr = bA + l * 256 + h * 32;
#pragma unroll
            for (int dv = 0; dv < 32; ++dv)
                kvv[dv] = fmaf(kk, vr[dv], kvv[dv]);
        }
        float* kvrow = KVs + (h * 32 + d) * 32;
#pragma unroll
        for (int dv = 0; dv < 32; ++dv) kvrow[dv] = kvv[dv];
    }
    __syncthreads();

    // ---- Q = elu(x@Wq)+1 -> bA (overwrites V) ----
    zero_acc(acc);
    gemm_k256(xs, Wq, 256, i, j, acc);
    store_acc<1>(bA, acc, i, j);
    __syncthreads();

    // ---- msg[l][c] = (Q[l,h,:]·KV[h][:,dv]) * L / (Q[l,h,:]·Ksum[h,:] + eps) -> bB ----
    {
        const int h = tid >> 5, dv = tid & 31, hb = (tid >> 5) << 5;
        (void)h;
        for (int l = 0; l < 64; ++l) {
            const float* qr = bA + l * 256 + hb;
            float s = 0.f, zd = 0.f;
#pragma unroll
            for (int d = 0; d < 32; ++d) {
                float q = qr[d];
                s  = fmaf(q, KVs[(hb + d) * 32 + dv], s);
                zd = fmaf(q, Ksum[hb + d], zd);
            }
            bB[l * 256 + tid] = s * 64.0f / (zd + 1e-6f);
        }
    }
    __syncthreads();

    // ---- m2 = msg @ Wm -> bA (overwrites Q) ----
    zero_acc(acc);
    gemm_k256(bB, Wm, 256, i, j, acc);
    store_acc<0>(bA, acc, i, j);
    __syncthreads();

    // ---- LN1 in-place on bA ----
    {
        const int wid = tid >> 5, lane = tid & 31;
        for (int rr = 0; rr < 8; ++rr) {
            int l = wid * 8 + rr;
            float* row = bA + l * 256;
            float4 u0 = *reinterpret_cast<float4*>(row + lane * 8);
            float4 u1 = *reinterpret_cast<float4*>(row + lane * 8 + 4);
            float s  = u0.x + u0.y + u0.z + u0.w + u1.x + u1.y + u1.z + u1.w;
            float ss = u0.x*u0.x + u0.y*u0.y + u0.z*u0.z + u0.w*u0.w
                     + u1.x*u1.x + u1.y*u1.y + u1.z*u1.z + u1.w*u1.w;
#pragma unroll
            for (int o = 16; o > 0; o >>= 1) {
                s  += __shfl_xor_sync(0xffffffffu, s,  o);
                ss += __shfl_xor_sync(0xffffffffu, ss, o);
            }
            float mean = s * (1.0f / 256.0f);
            float var  = ss * (1.0f / 256.0f) - mean * mean;
            float rstd = rsqrtf(var + 1e-5f);
            int c = lane * 8;
            float vv[8] = {u0.x,u0.y,u0.z,u0.w,u1.x,u1.y,u1.z,u1.w};
            float4 o0, o1;
            o0.x = (vv[0]-mean)*rstd*g1[c+0]+b1[c+0];
            o0.y = (vv[1]-mean)*rstd*g1[c+1]+b1[c+1];
            o0.z = (vv[2]-mean)*rstd*g1[c+2]+b1[c+2];
            o0.w = (vv[3]-mean)*rstd*g1[c+3]+b1[c+3];
            o1.x = (vv[4]-mean)*rstd*g1[c+4]+b1[c+4];
            o1.y = (vv[5]-mean)*rstd*g1[c+5]+b1[c+5];
            o1.z = (vv[6]-mean)*rstd*g1[c+6]+b1[c+6];
            o1.w = (vv[7]-mean)*rstd*g1[c+7]+b1[c+7];
            *reinterpret_cast<float4*>(row + lane * 8)     = o0;
            *reinterpret_cast<float4*>(row + lane * 8 + 4) = o1;
        }
    }
    __syncthreads();

    // ---- MLP: h = relu([xs | m2] @ W1), out2 = h @ W2, split over 256-col halves ----
    float acc2[16][4];
    zero_acc(acc2);

    // h1 = relu(xs @ W1[0:256, 0:256] + m2 @ W1[256:512, 0:256]) -> bB
    zero_acc(acc);
    gemm_k256(xs, W1, 512, i, j, acc);
    gemm_k256(bA, W1 + 256 * 512, 512, i, j, acc);
    store_acc<3>(bB, acc, i, j);
    __syncthreads();

    // acc2 += h1 @ W2[0:256, :]
    gemm_k256(bB, W2, 256, i, j, acc2);
    __syncthreads();

    // h2 = relu(xs @ W1[0:256, 256:512] + m2 @ W1[256:512, 256:512]) -> bB
    zero_acc(acc);
    gemm_k256(xs, W1 + 256, 512, i, j, acc);
    gemm_k256(bA, W1 + 256 * 512 + 256, 512, i, j, acc);
    store_acc<3>(bB, acc, i, j);
    __syncthreads();

    // acc2 += h2 @ W2[256:512, :]
    gemm_k256(bB, W2 + 256 * 256, 256, i, j, acc2);
    __syncthreads();

    // out2 -> bB
    store_acc<0>(bB, acc2, i, j);
    __syncthreads();

    // ---- LN2 + residual + scatter to out ----
    {
        const int wid = tid >> 5, lane = tid & 31;
        float* og = out + (size_t)bb * 57600 * 256;
        for (int rr = 0; rr < 8; ++rr) {
            int l = wid * 8 + rr;
            float* row = bB + l * 256;
            float4 u0 = *reinterpret_cast<float4*>(row + lane * 8);
            float4 u1 = *reinterpret_cast<float4*>(row + lane * 8 + 4);
            float s  = u0.x + u0.y + u0.z + u0.w + u1.x + u1.y + u1.z + u1.w;
            float ss = u0.x*u0.x + u0.y*u0.y + u0.z*u0.z + u0.w*u0.w
                     + u1.x*u1.x + u1.y*u1.y + u1.z*u1.z + u1.w*u1.w;
#pragma unroll
            for (int o = 16; o > 0; o >>= 1) {
                s  += __shfl_xor_sync(0xffffffffu, s,  o);
                ss += __shfl_xor_sync(0xffffffffu, ss, o);
            }
            float mean = s * (1.0f / 256.0f);
            float var  = ss * (1.0f / 256.0f) - mean * mean;
            float rstd = rsqrtf(var + 1e-5f);
            int c = lane * 8;
            const float* xr = xs + l * 256 + c;
            float vv[8] = {u0.x,u0.y,u0.z,u0.w,u1.x,u1.y,u1.z,u1.w};
            float4 o0, o1;
            o0.x = (vv[0]-mean)*rstd*g2[c+0]+b2[c+0] + xr[0];
            o0.y = (vv[1]-mean)*rstd*g2[c+1]+b2[c+1] + xr[1];
            o0.z = (vv[2]-mean)*rstd*g2[c+2]+b2[c+2] + xr[2];
            o0.w = (vv[3]-mean)*rstd*g2[c+3]+b2[c+3] + xr[3];
            o1.x = (vv[4]-mean)*rstd*g2[c+4]+b2[c+4] + xr[4];
            o1.y = (vv[5]-mean)*rstd*g2[c+5]+b2[c+5] + xr[5];
            o1.z = (vv[6]-mean)*rstd*g2[c+6]+b2[c+6] + xr[6];
            o1.w = (vv[7]-mean)*rstd*g2[c+7]+b2[c+7] + xr[7];
            int grow = (hi * 8 + (l >> 3)) * 240 + wi * 8 + (l & 7);
            float* orow = og + (size_t)grow * 256 + c;
            *reinterpret_cast<float4*>(orow)     = o0;
            *reinterpret_cast<float4*>(orow + 4) = o1;
        }
    }
}

extern "C" void kernel_launch(void* const* d_in, const int* in_sizes, int n_in,
                              void* d_out, int out_size)
{
    (void)in_sizes; (void)n_in; (void)out_size;
    const float* x  = (const float*)d_in[0];
    const float* Wq = (const float*)d_in[1];
    const float* Wk = (const float*)d_in[2];
    const float* Wv = (const float*)d_in[3];
    const float* Wm = (const float*)d_in[4];
    const float* W1 = (const float*)d_in[5];
    const float* W2 = (const float*)d_in[6];
    const float* g1 = (const float*)d_in[7];
    const float* b1 = (const float*)d_in[8];
    const float* g2 = (const float*)d_in[9];
    const float* b2 = (const float*)d_in[10];
    float* out = (float*)d_out;

    const size_t SMEM = 57600 * sizeof(float); // 230400 bytes
    cudaFuncSetAttribute(loftr_window_kernel,
                         cudaFuncAttributeMaxDynamicSharedMemorySize, (int)SMEM);
    loftr_window_kernel<<<3600, TPB, SMEM>>>(x, Wq, Wk, Wv, Wm, W1, W2,
                                             g1, b1, g2, b2, out);
}